// round 9
// baseline (speedup 1.0000x reference)
#include <cuda_runtime.h>
#include <cuda_bf16.h>
#include <cstdint>

typedef unsigned int u32;
typedef unsigned long long u64;

#define H 200
#define W 704
#define HW_TOT (H*W)
#define IHP 202
#define IWP 712
#define NPX ((size_t)IHP*IWP)
#define NCH 256
#define NBOX 128
#define NLAY 6

// ======================= persistent device scratch (zero-init at load) ==============
__device__ __align__(16) float g_f0[NPX*NCH];      // fp32 NHWC padded planes
__device__ __align__(16) float g_f1[NPX*NCH];
__device__ __align__(16) float g_fy[NPX*NCH];
__device__ __align__(16) char  g_qa[NPX*512];      // 2-limb s8 quantized input
__device__ float g_sa[IHP];                        // per-row activation scale
__device__ __align__(16) char  g_wq[(size_t)NLAY*9*4*32768];  // s8 weights
__device__ float g_wsc[NLAY*3*256];                // per (layer, kh, co) weight scale
__device__ float g_obj[NBOX*NCH];
__device__ float g_edge[NBOX*16];
__device__ int   g_nact;
__device__ int   g_pix[HW_TOT];
__device__ uint4 g_mask[HW_TOT];

// ======================= PTX helpers =======================
__device__ __forceinline__ u32 smem_to_u32(const void* p) {
    u32 a;
    asm("{ .reg .u64 t; cvta.to.shared.u64 t, %1; cvt.u32.u64 %0, t; }" : "=r"(a) : "l"(p));
    return a;
}
#define SWZ(o) ((o) ^ (((o) >> 3) & 0x70))

#define CP_ASYNC16(dst, src) \
    asm volatile("cp.async.cg.shared.global [%0], [%1], 16;" :: "r"(dst), "l"(src))
#define CP_COMMIT() asm volatile("cp.async.commit_group;" ::: "memory")
#define CP_WAIT1()  asm volatile("cp.async.wait_group 1;" ::: "memory")

#define LDSM4(r, addr) \
    asm volatile("ldmatrix.sync.aligned.m8n8.x4.shared.b16 {%0,%1,%2,%3}, [%4];" \
        : "=r"((r)[0]), "=r"((r)[1]), "=r"((r)[2]), "=r"((r)[3]) : "r"(addr))

#define IMMA(c, a, b0_, b1_) \
    asm volatile("mma.sync.aligned.m16n8k32.row.col.s32.s8.s8.s32 " \
        "{%0,%1,%2,%3},{%4,%5,%6,%7},{%8,%9},{%0,%1,%2,%3};" \
        : "+r"((c)[0]), "+r"((c)[1]), "+r"((c)[2]), "+r"((c)[3]) \
        : "r"((a)[0]), "r"((a)[1]), "r"((a)[2]), "r"((a)[3]), "r"(b0_), "r"(b1_))

// ======================= MLP =======================
__global__ void mlp_kernel(const float* __restrict__ box, const float* __restrict__ score,
                           const float* __restrict__ w1, const float* __restrict__ b1,
                           const float* __restrict__ w2, const float* __restrict__ b2,
                           const float* __restrict__ w3, const float* __restrict__ b3)
{
    __shared__ float f[25];
    __shared__ float h1[256];
    __shared__ float h2[256];
    int n = blockIdx.x, c = threadIdx.x;
    if (c < 25) f[c] = (c < 24) ? box[n * 24 + c] : score[n];
    __syncthreads();
    float a = b1[c];
#pragma unroll
    for (int k = 0; k < 25; ++k) a = fmaf(f[k], w1[k * 256 + c], a);
    h1[c] = fmaxf(a, 0.0f);
    __syncthreads();
    a = b2[c];
    for (int k = 0; k < 256; ++k) a = fmaf(h1[k], w2[k * 256 + c], a);
    h2[c] = fmaxf(a, 0.0f);
    __syncthreads();
    a = b3[c];
    for (int k = 0; k < 256; ++k) a = fmaf(h2[k], w3[k * 256 + c], a);
    g_obj[n * 256 + c] = a * score[n];
}

// ======================= box edges =======================
__global__ void edge_kernel(const float* __restrict__ box)
{
    int n = threadIdx.x;
    if (n == 0) g_nact = 0;
    if (n < NBOX) {
        float gx[4], gy[4];
#pragma unroll
        for (int e = 0; e < 4; ++e) {
            gx[e] = __fdiv_rn(__fsub_rn(box[n * 24 + e * 3 + 0], -140.8f), 0.4f);
            gy[e] = __fdiv_rn(__fsub_rn(box[n * 24 + e * 3 + 1], -40.0f), 0.4f);
        }
#pragma unroll
        for (int e = 0; e < 4; ++e) {
            int e1 = (e + 1) & 3;
            g_edge[n * 16 + e * 4 + 0] = gx[e];
            g_edge[n * 16 + e * 4 + 1] = gy[e];
            g_edge[n * 16 + e * 4 + 2] = __fsub_rn(gx[e1], gx[e]);
            g_edge[n * 16 + e * 4 + 3] = __fsub_rn(gy[e1], gy[e]);
        }
    }
}

// ======================= zero g_f0 =======================
__global__ void zero_kernel(float4* p, size_t n4)
{
    size_t i = (size_t)blockIdx.x * blockDim.x + threadIdx.x;
    size_t st = (size_t)gridDim.x * blockDim.x;
    float4 z = make_float4(0.f, 0.f, 0.f, 0.f);
    for (; i < n4; i += st) p[i] = z;
}

// ======================= raster mask + compaction =======================
__global__ void mask_kernel()
{
    __shared__ float se[NBOX * 16];
    int tid = threadIdx.x;
    for (int i = tid; i < NBOX * 16; i += blockDim.x) se[i] = g_edge[i];
    __syncthreads();

    int p = blockIdx.x * 256 + tid;
    if (p >= HW_TOT) return;
    int h = p / W;
    int w = p - h * W;
    float cy = (float)h + 0.5f;
    float cx = (float)w + 0.5f;

    unsigned mw[4];
    int cnt = 0;
#pragma unroll
    for (int wi = 0; wi < 4; ++wi) {
        unsigned m = 0;
        for (int b = 0; b < 32; ++b) {
            int n = wi * 32 + b;
            const float* e = &se[n * 16];
            bool ins = true;
#pragma unroll
            for (int k = 0; k < 4; ++k) {
                float ax = e[k * 4 + 0], ay = e[k * 4 + 1];
                float vx = e[k * 4 + 2], vy = e[k * 4 + 3];
                float c = __fsub_rn(__fmul_rn(vx, __fsub_rn(cy, ay)),
                                    __fmul_rn(vy, __fsub_rn(cx, ax)));
                ins = ins && (c >= 0.0f);
            }
            if (ins) m |= (1u << b);
        }
        mw[wi] = m;
        cnt += __popc(m);
    }
    if (cnt) {
        int pos = atomicAdd(&g_nact, 1);
        g_pix[pos] = p;
        g_mask[pos] = make_uint4(mw[0], mw[1], mw[2], mw[3]);
    }
}

// ======================= scatter into g_f0 (fp32 NHWC) =======================
__global__ void fill_kernel()
{
    int c = threadIdx.x;
    int nact = g_nact;
    for (int i = blockIdx.x; i < nact; i += gridDim.x) {
        int p = g_pix[i];
        uint4 mm = g_mask[i];
        int cnt = __popc(mm.x) + __popc(mm.y) + __popc(mm.z) + __popc(mm.w);
        float acc = 0.0f;
        unsigned m;
        m = mm.x; while (m) { int b = __ffs(m) - 1; m &= m - 1; acc += g_obj[(b)      * NCH + c]; }
        m = mm.y; while (m) { int b = __ffs(m) - 1; m &= m - 1; acc += g_obj[(b + 32) * NCH + c]; }
        m = mm.z; while (m) { int b = __ffs(m) - 1; m &= m - 1; acc += g_obj[(b + 64) * NCH + c]; }
        m = mm.w; while (m) { int b = __ffs(m) - 1; m &= m - 1; acc += g_obj[(b + 96) * NCH + c]; }
        int h = p / W;
        int w = p - h * W;
        g_f0[((size_t)(h + 1) * IWP + (w + 4)) * NCH + c] = acc / (float)cnt;
    }
}

// ======================= weight quantize: fp32 -> 2x s8 limbs ====================
// scale per (layer, kh-group, co); layout [l][tap][chunk]: 256co x (q1[64]|q0[64])
__global__ void wq_kernel(const float* __restrict__ cw)
{
    int blk = blockIdx.x;              // l*256 + co
    int l = blk >> 8, co = blk & 255;
    int ci = threadIdx.x;
    __shared__ float red[256];
    __shared__ float gsc[3];

    float w[9];
    const float* src = cw + (((size_t)(l * 256 + co)) * 256 + ci) * 9;
#pragma unroll
    for (int t = 0; t < 9; ++t) w[t] = src[t];

    for (int g = 0; g < 3; ++g) {
        float m = fmaxf(fabsf(w[g * 3]), fmaxf(fabsf(w[g * 3 + 1]), fabsf(w[g * 3 + 2])));
        red[ci] = m;
        __syncthreads();
        for (int s = 128; s > 0; s >>= 1) {
            if (ci < s) red[ci] = fmaxf(red[ci], red[ci + s]);
            __syncthreads();
        }
        if (ci == 0) {
            float rmax = red[0];
            float sc = (rmax > 1e-30f) ? rmax * (1.0f / 16256.0f) : 1.0f;
            gsc[g] = sc;
            g_wsc[(l * 3 + g) * 256 + co] = sc;
        }
        __syncthreads();
    }
#pragma unroll
    for (int t = 0; t < 9; ++t) {
        float inv = 1.0f / gsc[t / 3];
        float v = w[t] * inv;
        float q1f = rintf(v * 0.0078125f);
        float q0f = rintf(fmaf(-128.0f, q1f, v));
        size_t base = ((size_t)(l * 9 + t) * 4 + (ci >> 6)) * 32768 + (size_t)co * 128 + (ci & 63);
        g_wq[base]      = (char)(int)q1f;
        g_wq[base + 64] = (char)(int)q0f;
    }
}

// ======================= activation quantize: per padded image row ==================
__global__ void quant_kernel(const float* __restrict__ plane)
{
    __shared__ float red[256];
    int row = blockIdx.x, tid = threadIdx.x;
    const float* rp = plane + (size_t)row * IWP * 256;
    float mx = 0.0f;
    for (int i = tid; i < IWP * 256; i += 256) mx = fmaxf(mx, fabsf(rp[i]));
    red[tid] = mx;
    __syncthreads();
    for (int s = 128; s > 0; s >>= 1) {
        if (tid < s) red[tid] = fmaxf(red[tid], red[tid + s]);
        __syncthreads();
    }
    float rmax = red[0];
    float sc = (rmax > 1e-30f) ? rmax * (1.0f / 16256.0f) : 1.0f;
    if (tid == 0) g_sa[row] = sc;
    float inv = 1.0f / sc;

    char* qrow = g_qa + (size_t)row * IWP * 512;
    for (int g = tid; g < IWP * 64; g += 256) {
        int col = g >> 6, c4 = g & 63;
        float4 x = *(const float4*)(rp + col * 256 + c4 * 4);
        float xv[4] = {x.x, x.y, x.z, x.w};
        u32 p1 = 0, p0 = 0;
#pragma unroll
        for (int k = 0; k < 4; ++k) {
            float t = xv[k] * inv;
            float q1f = rintf(t * 0.0078125f);
            float q0f = rintf(fmaf(-128.0f, q1f, t));
            p1 |= ((u32)((int)q1f) & 0xffu) << (k * 8);
            p0 |= ((u32)((int)q0f) & 0xffu) << (k * 8);
        }
        int chunk = c4 >> 4;
        int off = (c4 & 15) * 4;
        char* base = qrow + (size_t)col * 512 + chunk * 128;
        *(u32*)(base + off)      = p1;
        *(u32*)(base + 64 + off) = p0;
    }
}

// ======================= int8 IMMA conv3x3 + dequant + BN (+res) + ReLU ============
// CTA: 256 thr (8 warps, 2 wm x 4 wn; warp tile m32 x n64).
// Tile: M=64 px (one row) x N=256 co. 36 stages = 9 taps x 4 ci-chunks(64).
// Stage: A 8K (64 px x [q1 64B|q0 64B]) + B 32K (256 co x [q1|q0]). 3-buffer, 1 sync.
// s32 accumulators acc_hi (w 16384) / acc_mid (w 128); dequant to f32 per kh-group.
#define STG 40960
#define NBUF 3
#define SMEM_CONV (NBUF*STG + 5120 + 128)

__device__ __forceinline__ void issue_stage(
    u32 db, int it, int h0, int w0, int tid,
    const char* __restrict__ qa, const char* __restrict__ wqL)
{
    int tap = it >> 2, chunk = it & 3;
    int kh = tap / 3, kw = tap - kh * 3;
    u32 Ab = db + (it % NBUF) * STG;
    u32 Bb = Ab + 8192;
    // A: 64 px rows x 128B
    size_t abase = ((size_t)(h0 + kh) * IWP + (size_t)(w0 + 3 + kw)) * 512 + chunk * 128;
#pragma unroll
    for (int k = 0; k < 2; ++k) {
        int idx = tid + k * 256;           // 0..511
        int m = idx >> 3, j = idx & 7;
        CP_ASYNC16(Ab + SWZ((u32)(m * 128 + j * 16)), qa + abase + (size_t)m * 512 + j * 16);
    }
    // B: 256 co rows x 128B
    const char* wsrc = wqL + (size_t)(tap * 4 + chunk) * 32768;
#pragma unroll
    for (int k = 0; k < 8; ++k) {
        int idx = tid + k * 256;           // 0..2047
        int co = idx >> 3, j = idx & 7;
        CP_ASYNC16(Bb + SWZ((u32)(co * 128 + j * 16)), wsrc + (size_t)co * 128 + j * 16);
    }
}

__global__ __launch_bounds__(256)
void conv_imma(const char* __restrict__ qa, const float* __restrict__ sa,
               const char* __restrict__ wqL, const float* __restrict__ wscL,
               const float* __restrict__ bng, const float* __restrict__ bnb,
               const float* __restrict__ bnm, const float* __restrict__ bnv,
               const float* __restrict__ resF, float* outF, float* outC)
{
    extern __shared__ char smem_raw[];
    u32 sb = smem_to_u32(smem_raw);
    u32 pd = (128u - (sb & 127u)) & 127u;
    char* dyn = smem_raw + pd;
    u32 db = sb + pd;
    float* ssc = (float*)(dyn + NBUF * STG);
    float* ssh = ssc + 256;
    float* sws = ssh + 256;    // [3][256]

    int tid  = threadIdx.x;
    int lane = tid & 31, warp = tid >> 5;
    int wm = warp & 1, wn = warp >> 1;       // 2 x 4 warp grid
    int h0 = blockIdx.y;
    int w0 = blockIdx.x * 64;

    {
        float scv = bng[tid] * rsqrtf(bnv[tid] + 1e-5f);
        ssc[tid] = scv;
        ssh[tid] = bnb[tid] - bnm[tid] * scv;
#pragma unroll
        for (int g = 0; g < 3; ++g) sws[g * 256 + tid] = wscL[g * 256 + tid];
    }

    int acch[2][8][4];
    int accm[2][8][4];
    float accf[2][8][4];
#pragma unroll
    for (int a = 0; a < 2; ++a)
#pragma unroll
        for (int b = 0; b < 8; ++b)
#pragma unroll
            for (int c = 0; c < 4; ++c) { acch[a][b][c] = 0; accm[a][b][c] = 0; accf[a][b][c] = 0.0f; }

    issue_stage(db, 0, h0, w0, tid, qa, wqL); CP_COMMIT();
    issue_stage(db, 1, h0, w0, tid, qa, wqL); CP_COMMIT();

    int lrow = lane & 15;
    int lkb  = (lane >> 4) << 4;

    for (int it = 0; it < 36; ++it) {
        CP_WAIT1();
        __syncthreads();
        if (it + 2 < 36) issue_stage(db, it + 2, h0, w0, tid, qa, wqL);
        CP_COMMIT();

        u32 Ab = db + (it % NBUF) * STG;
        u32 Bb = Ab + 8192;

#pragma unroll
        for (int kst = 0; kst < 2; ++kst) {
            int kb = kst * 32 + lkb;
            u32 a1[2][4], a0[2][4];
#pragma unroll
            for (int mf = 0; mf < 2; ++mf) {
                u32 ro = (u32)((wm * 32 + mf * 16 + lrow) * 128);
                LDSM4(a1[mf], Ab + SWZ(ro + kb));
                LDSM4(a0[mf], Ab + SWZ(ro + kb + 64));
            }
#pragma unroll
            for (int bq = 0; bq < 4; ++bq) {
                u32 b1[4], b0[4];
                u32 nro = (u32)((wn * 64 + bq * 16 + lrow) * 128);
                LDSM4(b1, Bb + SWZ(nro + kb));
                LDSM4(b0, Bb + SWZ(nro + kb + 64));
#pragma unroll
                for (int mf = 0; mf < 2; ++mf) {
#pragma unroll
                    for (int j = 0; j < 2; ++j) {
                        IMMA(acch[mf][2 * bq + j], a1[mf], b1[j], b1[j + 2]);
                        IMMA(accm[mf][2 * bq + j], a1[mf], b0[j], b0[j + 2]);
                        IMMA(accm[mf][2 * bq + j], a0[mf], b1[j], b1[j + 2]);
                    }
                }
            }
        }

        if ((it == 11) | (it == 23) | (it == 35)) {
            int kh = it / 12;
            float sag = sa[h0 + kh];
            const float* swr = sws + kh * 256;
#pragma unroll
            for (int mf = 0; mf < 2; ++mf) {
#pragma unroll
                for (int t = 0; t < 8; ++t) {
                    int n0 = wn * 64 + t * 8 + (lane & 3) * 2;
                    float swA = sag * swr[n0];
                    float swB = sag * swr[n0 + 1];
                    accf[mf][t][0] += swA * fmaf(16384.f, (float)acch[mf][t][0], 128.f * (float)accm[mf][t][0]);
                    accf[mf][t][1] += swB * fmaf(16384.f, (float)acch[mf][t][1], 128.f * (float)accm[mf][t][1]);
                    accf[mf][t][2] += swA * fmaf(16384.f, (float)acch[mf][t][2], 128.f * (float)accm[mf][t][2]);
                    accf[mf][t][3] += swB * fmaf(16384.f, (float)acch[mf][t][3], 128.f * (float)accm[mf][t][3]);
#pragma unroll
                    for (int c = 0; c < 4; ++c) { acch[mf][t][c] = 0; accm[mf][t][c] = 0; }
                }
            }
        }
    }

    // ---- epilogue: BN, residual, ReLU, store ----
#pragma unroll
    for (int mf = 0; mf < 2; ++mf) {
#pragma unroll
        for (int r2 = 0; r2 < 2; ++r2) {
            int m = wm * 32 + mf * 16 + (lane >> 2) + r2 * 8;
            int wpix = w0 + m;
            size_t pb = ((size_t)(h0 + 1) * IWP + (size_t)(wpix + 4)) * NCH;
#pragma unroll
            for (int t = 0; t < 8; ++t) {
                int n = wn * 64 + t * 8 + (lane & 3) * 2;
                float v0 = fmaf(accf[mf][t][r2 * 2 + 0], ssc[n],     ssh[n]);
                float v1 = fmaf(accf[mf][t][r2 * 2 + 1], ssc[n + 1], ssh[n + 1]);
                if (resF) {
                    v0 += resF[pb + n];
                    v1 += resF[pb + n + 1];
                }
                v0 = fmaxf(v0, 0.0f);
                v1 = fmaxf(v1, 0.0f);
                if (outF) {
                    outF[pb + n]     = v0;
                    outF[pb + n + 1] = v1;
                } else {
                    outC[(size_t)n * HW_TOT       + (size_t)h0 * W + wpix] = v0;
                    outC[(size_t)(n + 1) * HW_TOT + (size_t)h0 * W + wpix] = v1;
                }
            }
        }
    }
}

// ======================= host launcher =======================
extern "C" void kernel_launch(void* const* d_in, const int* in_sizes, int n_in,
                              void* d_out, int out_size)
{
    const float* box   = (const float*)d_in[0];
    const float* score = (const float*)d_in[1];
    const float* w1 = (const float*)d_in[2];
    const float* b1 = (const float*)d_in[3];
    const float* w2 = (const float*)d_in[4];
    const float* b2 = (const float*)d_in[5];
    const float* w3 = (const float*)d_in[6];
    const float* b3 = (const float*)d_in[7];
    const float* cw = (const float*)d_in[8];
    const float* bg = (const float*)d_in[9];
    const float* bb = (const float*)d_in[10];
    const float* bm = (const float*)d_in[11];
    const float* bv = (const float*)d_in[12];

    cudaFuncSetAttribute(conv_imma, cudaFuncAttributeMaxDynamicSharedMemorySize, SMEM_CONV);

    float *f0, *f1, *fy, *saP, *wscP;
    char *qaP, *wqP;
    cudaGetSymbolAddress((void**)&f0,  g_f0);
    cudaGetSymbolAddress((void**)&f1,  g_f1);
    cudaGetSymbolAddress((void**)&fy,  g_fy);
    cudaGetSymbolAddress((void**)&qaP, g_qa);
    cudaGetSymbolAddress((void**)&saP, g_sa);
    cudaGetSymbolAddress((void**)&wqP, g_wq);
    cudaGetSymbolAddress((void**)&wscP, g_wsc);

    mlp_kernel<<<128, 256>>>(box, score, w1, b1, w2, b2, w3, b3);
    edge_kernel<<<1, 128>>>(box);
    wq_kernel<<<NLAY * 256, 256>>>(cw);
    zero_kernel<<<2048, 256>>>((float4*)f0, NPX * NCH / 4);
    mask_kernel<<<HW_TOT / 256, 256>>>();
    fill_kernel<<<1024, 256>>>();

    dim3 grid(11, 200);
    const size_t WQL = (size_t)9 * 4 * 32768;
    const float* planes_in[6]  = { f0, fy, f1, fy, f0, fy };
    float*       planes_out[6] = { fy, f1, fy, f0, fy, nullptr };
    const float* planes_res[6] = { nullptr, f0, nullptr, f1, nullptr, f0 };

    for (int l = 0; l < 6; ++l) {
        quant_kernel<<<IHP, 256>>>(planes_in[l]);
        conv_imma<<<grid, 256, SMEM_CONV>>>(
            qaP, saP, wqP + l * WQL, wscP + l * 768,
            bg + l * 256, bb + l * 256, bm + l * 256, bv + l * 256,
            planes_res[l], planes_out[l], (float*)d_out);
    }
}

// round 10
// speedup vs baseline: 2.8605x; 2.8605x over previous
#include <cuda_runtime.h>
#include <cuda_bf16.h>
#include <cstdint>

typedef unsigned int u32;
typedef unsigned long long u64;

#define H 200
#define W 704
#define HW_TOT (H*W)            // 140800
#define IHP 202
#define IWP 712
#define NPX ((size_t)IHP*IWP)   // padded pixels per plane
#define NCH 256
#define NBOX 128
#define NLAY 6

// ======================= persistent device scratch (zero-init at load) ==============
__device__ __align__(16) __nv_bfloat16 g_p0h[NPX*NCH], g_p0l[NPX*NCH];
__device__ __align__(16) __nv_bfloat16 g_p1h[NPX*NCH], g_p1l[NPX*NCH];
__device__ __align__(16) __nv_bfloat16 g_yh [NPX*NCH], g_yl [NPX*NCH];
__device__ __align__(16) __nv_bfloat16 g_wh[(size_t)NLAY*9*65536];
__device__ __align__(16) __nv_bfloat16 g_wl[(size_t)NLAY*9*65536];
__device__ float g_obj[NBOX*NCH];
__device__ float g_edge[NBOX*16];
__device__ int   g_nact;
__device__ int   g_pix[HW_TOT];
__device__ uint4 g_mask[HW_TOT];

// ======================= PTX helpers (plain sm_80-class PTX) =======================
__device__ __forceinline__ u32 smem_to_u32(const void* p) {
    u32 a;
    asm("{ .reg .u64 t; cvta.to.shared.u64 t, %1; cvt.u32.u64 %0, t; }" : "=r"(a) : "l"(p));
    return a;
}
#define SWZ(o) ((o) ^ (((o) >> 3) & 0x70))

#define CP_ASYNC16(dst, src) \
    asm volatile("cp.async.cg.shared.global [%0], [%1], 16;" :: "r"(dst), "l"(src))
#define CP_COMMIT() asm volatile("cp.async.commit_group;" ::: "memory")
#define CP_WAIT1()  asm volatile("cp.async.wait_group 1;" ::: "memory")
#define CP_WAIT0()  asm volatile("cp.async.wait_group 0;" ::: "memory")

#define LDSM4(r, addr) \
    asm volatile("ldmatrix.sync.aligned.m8n8.x4.shared.b16 {%0,%1,%2,%3}, [%4];" \
        : "=r"((r)[0]), "=r"((r)[1]), "=r"((r)[2]), "=r"((r)[3]) : "r"(addr))

#define MMA16816(c, a, b0_, b1_) \
    asm volatile("mma.sync.aligned.m16n8k16.row.col.f32.bf16.bf16.f32 " \
        "{%0,%1,%2,%3},{%4,%5,%6,%7},{%8,%9},{%0,%1,%2,%3};" \
        : "+f"((c)[0]), "+f"((c)[1]), "+f"((c)[2]), "+f"((c)[3]) \
        : "r"((a)[0]), "r"((a)[1]), "r"((a)[2]), "r"((a)[3]), "r"(b0_), "r"(b1_))

__device__ __forceinline__ float bfu(u32 bits16) { return __uint_as_float(bits16 << 16); }

// ======================= MLP =======================
__global__ void mlp_kernel(const float* __restrict__ box, const float* __restrict__ score,
                           const float* __restrict__ w1, const float* __restrict__ b1,
                           const float* __restrict__ w2, const float* __restrict__ b2,
                           const float* __restrict__ w3, const float* __restrict__ b3)
{
    __shared__ float f[25];
    __shared__ float h1[256];
    __shared__ float h2[256];
    int n = blockIdx.x, c = threadIdx.x;
    if (c < 25) f[c] = (c < 24) ? box[n * 24 + c] : score[n];
    __syncthreads();
    float a = b1[c];
#pragma unroll
    for (int k = 0; k < 25; ++k) a = fmaf(f[k], w1[k * 256 + c], a);
    h1[c] = fmaxf(a, 0.0f);
    __syncthreads();
    a = b2[c];
    for (int k = 0; k < 256; ++k) a = fmaf(h1[k], w2[k * 256 + c], a);
    h2[c] = fmaxf(a, 0.0f);
    __syncthreads();
    a = b3[c];
    for (int k = 0; k < 256; ++k) a = fmaf(h2[k], w3[k * 256 + c], a);
    g_obj[n * 256 + c] = a * score[n];
}

// ======================= box edges =======================
__global__ void edge_kernel(const float* __restrict__ box)
{
    int n = threadIdx.x;
    if (n == 0) g_nact = 0;
    if (n < NBOX) {
        float gx[4], gy[4];
#pragma unroll
        for (int e = 0; e < 4; ++e) {
            gx[e] = __fdiv_rn(__fsub_rn(box[n * 24 + e * 3 + 0], -140.8f), 0.4f);
            gy[e] = __fdiv_rn(__fsub_rn(box[n * 24 + e * 3 + 1], -40.0f), 0.4f);
        }
#pragma unroll
        for (int e = 0; e < 4; ++e) {
            int e1 = (e + 1) & 3;
            g_edge[n * 16 + e * 4 + 0] = gx[e];
            g_edge[n * 16 + e * 4 + 1] = gy[e];
            g_edge[n * 16 + e * 4 + 2] = __fsub_rn(gx[e1], gx[e]);
            g_edge[n * 16 + e * 4 + 3] = __fsub_rn(gy[e1], gy[e]);
        }
    }
}

// ======================= zero p0 planes =======================
__global__ void zero2_kernel(uint4* a, uint4* b, size_t n4)
{
    size_t i = (size_t)blockIdx.x * blockDim.x + threadIdx.x;
    size_t st = (size_t)gridDim.x * blockDim.x;
    uint4 z = make_uint4(0, 0, 0, 0);
    for (; i < n4; i += st) { a[i] = z; b[i] = z; }
}

// ======================= raster mask + compaction =======================
__global__ void mask_kernel()
{
    __shared__ float se[NBOX * 16];
    int tid = threadIdx.x;
    for (int i = tid; i < NBOX * 16; i += blockDim.x) se[i] = g_edge[i];
    __syncthreads();

    int p = blockIdx.x * 256 + tid;
    if (p >= HW_TOT) return;
    int h = p / W;
    int w = p - h * W;
    float cy = (float)h + 0.5f;
    float cx = (float)w + 0.5f;

    unsigned mw[4];
    int cnt = 0;
#pragma unroll
    for (int wi = 0; wi < 4; ++wi) {
        unsigned m = 0;
        for (int b = 0; b < 32; ++b) {
            int n = wi * 32 + b;
            const float* e = &se[n * 16];
            bool ins = true;
#pragma unroll
            for (int k = 0; k < 4; ++k) {
                float ax = e[k * 4 + 0], ay = e[k * 4 + 1];
                float vx = e[k * 4 + 2], vy = e[k * 4 + 3];
                float c = __fsub_rn(__fmul_rn(vx, __fsub_rn(cy, ay)),
                                    __fmul_rn(vy, __fsub_rn(cx, ax)));
                ins = ins && (c >= 0.0f);
            }
            if (ins) m |= (1u << b);
        }
        mw[wi] = m;
        cnt += __popc(m);
    }
    if (cnt) {
        int pos = atomicAdd(&g_nact, 1);
        g_pix[pos] = p;
        g_mask[pos] = make_uint4(mw[0], mw[1], mw[2], mw[3]);
    }
}

// ======================= scatter into p0 (bf16 hi/lo NHWC) =======================
__global__ void fill_kernel()
{
    int c = threadIdx.x;
    int nact = g_nact;
    for (int i = blockIdx.x; i < nact; i += gridDim.x) {
        int p = g_pix[i];
        uint4 mm = g_mask[i];
        int cnt = __popc(mm.x) + __popc(mm.y) + __popc(mm.z) + __popc(mm.w);
        float acc = 0.0f;
        unsigned m;
        m = mm.x; while (m) { int b = __ffs(m) - 1; m &= m - 1; acc += g_obj[(b)      * NCH + c]; }
        m = mm.y; while (m) { int b = __ffs(m) - 1; m &= m - 1; acc += g_obj[(b + 32) * NCH + c]; }
        m = mm.z; while (m) { int b = __ffs(m) - 1; m &= m - 1; acc += g_obj[(b + 64) * NCH + c]; }
        m = mm.w; while (m) { int b = __ffs(m) - 1; m &= m - 1; acc += g_obj[(b + 96) * NCH + c]; }
        float v = acc / (float)cnt;
        __nv_bfloat16 hb = __float2bfloat16(v);
        __nv_bfloat16 lb = __float2bfloat16(v - __bfloat162float(hb));
        int h = p / W;
        int w = p - h * W;
        size_t o = ((size_t)(h + 1) * IWP + (w + 4)) * NCH + c;
        g_p0h[o] = hb;
        g_p0l[o] = lb;
    }
}

// ======================= weight split fp32 -> bf16 hi/lo, [layer][tap][co][ci] ========
__global__ void wsplit_kernel(const float* __restrict__ cw)
{
    int idx = blockIdx.x * 256 + threadIdx.x;
    if (idx >= NLAY * 65536) return;
    int l = idx >> 16;
    int r = idx & 65535;           // co*256 + ci
    int co = r >> 8, ci = r & 255;
    const float* src = cw + (((size_t)l * 256 + co) * 256 + ci) * 9;
#pragma unroll
    for (int t = 0; t < 9; ++t) {
        float v = src[t];
        __nv_bfloat16 hb = __float2bfloat16(v);
        __nv_bfloat16 lb = __float2bfloat16(v - __bfloat162float(hb));
        size_t dst = (size_t)(l * 9 + t) * 65536 + r;
        g_wh[dst] = hb;
        g_wl[dst] = lb;
    }
}

// ======================= mma.sync conv3x3 + BN (+res) + ReLU =======================
// CTA: 256 thr (8 warps, 2 wm x 4 wn; warp tile m=32 x n=64), 2 CTAs/SM.
// Tile: M=64 px x N=256 co. 72 stages = 9 taps x 8 ci-chunks(32).
// Stage: A 8K (64 px rows of [hi64B|lo64B]) + B 32K (256 co rows of [hi|lo]).
// Double-buffered (80KB/CTA), R6 pipeline (2 syncs/stage); cross-CTA overlap covers bubbles.
#define STG 40960
#define SMEM_CONV (2*STG + 2048 + 128)

__device__ __forceinline__ void issue_stage(
    u32 db, int buf, int it, int h0, int w0, int tid,
    const __nv_bfloat16* __restrict__ inH, const __nv_bfloat16* __restrict__ inL,
    const __nv_bfloat16* __restrict__ wH,  const __nv_bfloat16* __restrict__ wL)
{
    int tap = it >> 3, q = it & 7;
    int kh = tap / 3, kw = tap - kh * 3;
    int ci0 = q * 32;
    u32 Ab = db + buf * STG;
    u32 Bb = Ab + 8192;
    // A: 64 px rows x 128B [hi64|lo64]; 512 chunks, 2/thread
    size_t abase = ((size_t)(h0 + kh) * IWP + (size_t)(w0 + 3 + kw)) * NCH + ci0;
#pragma unroll
    for (int k = 0; k < 2; ++k) {
        int idx = tid + k * 256;           // 0..511
        int m = idx >> 3, j = idx & 7;
        size_t gb = abase + (size_t)m * NCH + (j & 3) * 8;
        const __nv_bfloat16* src = (j < 4) ? (inH + gb) : (inL + gb);
        CP_ASYNC16(Ab + SWZ((u32)(m * 128 + j * 16)), src);
    }
    // B: 256 co rows x 128B [hi64|lo64]; 2048 chunks, 8/thread
    size_t wbase = (size_t)tap * 65536 + ci0;
#pragma unroll
    for (int k = 0; k < 8; ++k) {
        int idx = tid + k * 256;           // 0..2047
        int co = idx >> 3, j = idx & 7;
        size_t gb = wbase + (size_t)co * 256 + (j & 3) * 8;
        const __nv_bfloat16* src = (j < 4) ? (wH + gb) : (wL + gb);
        CP_ASYNC16(Bb + SWZ((u32)(co * 128 + j * 16)), src);
    }
}

__global__ __launch_bounds__(256, 2)
void conv_mma(const __nv_bfloat16* __restrict__ inH, const __nv_bfloat16* __restrict__ inL,
              const __nv_bfloat16* __restrict__ wH,  const __nv_bfloat16* __restrict__ wL,
              const float* __restrict__ bng, const float* __restrict__ bnb,
              const float* __restrict__ bnm, const float* __restrict__ bnv,
              const __nv_bfloat16* resH, const __nv_bfloat16* resL,
              __nv_bfloat16* outH, __nv_bfloat16* outL, float* outF)
{
    extern __shared__ char smem_raw[];
    u32 sb = smem_to_u32(smem_raw);
    u32 pd = (128u - (sb & 127u)) & 127u;
    char* dyn = smem_raw + pd;
    u32 db = sb + pd;
    float* ssc = (float*)(dyn + 2 * STG);
    float* ssh = ssc + 256;

    int tid  = threadIdx.x;
    int lane = tid & 31, warp = tid >> 5;
    int wm = warp & 1, wn = warp >> 1;          // 2 x 4 warp grid
    int h0 = blockIdx.y;
    int w0 = blockIdx.x * 64;                   // 11 * 64 = 704 exact

    {   // BN affine per channel
        int c = tid;
        float sc = bng[c] * rsqrtf(bnv[c] + 1e-5f);
        ssc[c] = sc;
        ssh[c] = bnb[c] - bnm[c] * sc;
    }

    float acc[2][8][4];
#pragma unroll
    for (int a = 0; a < 2; ++a)
#pragma unroll
        for (int b = 0; b < 8; ++b)
#pragma unroll
            for (int c = 0; c < 4; ++c) acc[a][b][c] = 0.0f;

    issue_stage(db, 0, 0, h0, w0, tid, inH, inL, wH, wL);
    CP_COMMIT();

    int lrow = lane & 15;
    int lkb  = (lane >> 4) << 4;       // 0 or 16 bytes (k0/k8)

    for (int it = 0; it < 72; ++it) {
        if (it + 1 < 72) {
            issue_stage(db, (it + 1) & 1, it + 1, h0, w0, tid, inH, inL, wH, wL);
            CP_COMMIT();
            CP_WAIT1();
        } else {
            CP_WAIT0();
        }
        __syncthreads();

        u32 Ab = db + (it & 1) * STG;
        u32 Bb = Ab + 8192;

#pragma unroll
        for (int st = 0; st < 2; ++st) {
            int kb = st * 32 + lkb;
            u32 afh[2][4], afl[2][4];
#pragma unroll
            for (int mf = 0; mf < 2; ++mf) {
                u32 ro = (u32)((wm * 32 + mf * 16 + lrow) * 128);
                LDSM4(afh[mf], Ab + SWZ(ro + kb));
                LDSM4(afl[mf], Ab + SWZ(ro + kb + 64));
            }
#pragma unroll
            for (int bp = 0; bp < 4; ++bp) {
                u32 bh[4], bl[4];
                u32 nro = (u32)((wn * 64 + bp * 16 + lrow) * 128);
                LDSM4(bh, Bb + SWZ(nro + kb));
                LDSM4(bl, Bb + SWZ(nro + kb + 64));
#pragma unroll
                for (int mf = 0; mf < 2; ++mf) {
                    MMA16816(acc[mf][2 * bp],     afh[mf], bh[0], bh[2]);
                    MMA16816(acc[mf][2 * bp + 1], afh[mf], bh[1], bh[3]);
                }
#pragma unroll
                for (int mf = 0; mf < 2; ++mf) {
                    MMA16816(acc[mf][2 * bp],     afl[mf], bh[0], bh[2]);
                    MMA16816(acc[mf][2 * bp + 1], afl[mf], bh[1], bh[3]);
                }
#pragma unroll
                for (int mf = 0; mf < 2; ++mf) {
                    MMA16816(acc[mf][2 * bp],     afh[mf], bl[0], bl[2]);
                    MMA16816(acc[mf][2 * bp + 1], afh[mf], bl[1], bl[3]);
                }
            }
        }
        __syncthreads();
    }

    // ---- epilogue: BN, residual, ReLU, store ----
#pragma unroll
    for (int mf = 0; mf < 2; ++mf) {
#pragma unroll
        for (int r2 = 0; r2 < 2; ++r2) {
            int m = wm * 32 + mf * 16 + (lane >> 2) + r2 * 8;
            int wpix = w0 + m;
            size_t pb = ((size_t)(h0 + 1) * IWP + (size_t)(wpix + 4)) * NCH;
#pragma unroll
            for (int a = 0; a < 8; ++a) {
                int n = wn * 64 + a * 8 + (lane & 3) * 2;
                float v0 = fmaf(acc[mf][a][r2 * 2 + 0], ssc[n],     ssh[n]);
                float v1 = fmaf(acc[mf][a][r2 * 2 + 1], ssc[n + 1], ssh[n + 1]);
                if (resH) {
                    u32 rh = *(const u32*)((const char*)resH + (pb + n) * 2);
                    u32 rl = *(const u32*)((const char*)resL + (pb + n) * 2);
                    v0 += bfu(rh & 0xffffu) + bfu(rl & 0xffffu);
                    v1 += bfu(rh >> 16)     + bfu(rl >> 16);
                }
                v0 = fmaxf(v0, 0.0f);
                v1 = fmaxf(v1, 0.0f);
                if (outH) {
                    __nv_bfloat16 hb0 = __float2bfloat16(v0);
                    __nv_bfloat16 hb1 = __float2bfloat16(v1);
                    __nv_bfloat16 lb0 = __float2bfloat16(v0 - __bfloat162float(hb0));
                    __nv_bfloat16 lb1 = __float2bfloat16(v1 - __bfloat162float(hb1));
                    u32 hp = (u32)__bfloat16_as_ushort(hb0) | ((u32)__bfloat16_as_ushort(hb1) << 16);
                    u32 lp = (u32)__bfloat16_as_ushort(lb0) | ((u32)__bfloat16_as_ushort(lb1) << 16);
                    *(u32*)((char*)outH + (pb + n) * 2) = hp;
                    *(u32*)((char*)outL + (pb + n) * 2) = lp;
                } else {
                    outF[(size_t)n * HW_TOT       + (size_t)h0 * W + wpix] = v0;
                    outF[(size_t)(n + 1) * HW_TOT + (size_t)h0 * W + wpix] = v1;
                }
            }
        }
    }
}

// ======================= host launcher =======================
extern "C" void kernel_launch(void* const* d_in, const int* in_sizes, int n_in,
                              void* d_out, int out_size)
{
    const float* box   = (const float*)d_in[0];
    const float* score = (const float*)d_in[1];
    const float* w1 = (const float*)d_in[2];
    const float* b1 = (const float*)d_in[3];
    const float* w2 = (const float*)d_in[4];
    const float* b2 = (const float*)d_in[5];
    const float* w3 = (const float*)d_in[6];
    const float* b3 = (const float*)d_in[7];
    const float* cw = (const float*)d_in[8];
    const float* bg = (const float*)d_in[9];
    const float* bb = (const float*)d_in[10];
    const float* bm = (const float*)d_in[11];
    const float* bv = (const float*)d_in[12];

    cudaFuncSetAttribute(conv_mma, cudaFuncAttributeMaxDynamicSharedMemorySize, SMEM_CONV);

    __nv_bfloat16 *p0h, *p0l, *p1h, *p1l, *yh, *yl, *wh, *wl;
    cudaGetSymbolAddress((void**)&p0h, g_p0h);
    cudaGetSymbolAddress((void**)&p0l, g_p0l);
    cudaGetSymbolAddress((void**)&p1h, g_p1h);
    cudaGetSymbolAddress((void**)&p1l, g_p1l);
    cudaGetSymbolAddress((void**)&yh,  g_yh);
    cudaGetSymbolAddress((void**)&yl,  g_yl);
    cudaGetSymbolAddress((void**)&wh,  g_wh);
    cudaGetSymbolAddress((void**)&wl,  g_wl);

    mlp_kernel<<<128, 256>>>(box, score, w1, b1, w2, b2, w3, b3);
    edge_kernel<<<1, 128>>>(box);
    wsplit_kernel<<<(NLAY * 65536 + 255) / 256, 256>>>(cw);
    zero2_kernel<<<2048, 256>>>((uint4*)p0h, (uint4*)p0l, NPX * NCH / 8);
    mask_kernel<<<HW_TOT / 256, 256>>>();
    fill_kernel<<<1024, 256>>>();

    dim3 grid(11, 200);      // 11 w-tiles(64) x 200 rows
    const size_t WSTRIDE = (size_t)9 * 65536;
    // blk0: p0 -> y ; (y, res p0) -> p1
    conv_mma<<<grid, 256, SMEM_CONV>>>(p0h, p0l, wh + 0 * WSTRIDE, wl + 0 * WSTRIDE,
        bg + 0, bb + 0, bm + 0, bv + 0, nullptr, nullptr, yh, yl, nullptr);
    conv_mma<<<grid, 256, SMEM_CONV>>>(yh, yl, wh + 1 * WSTRIDE, wl + 1 * WSTRIDE,
        bg + 256, bb + 256, bm + 256, bv + 256, p0h, p0l, p1h, p1l, nullptr);
    // blk1: p1 -> y ; (y, res p1) -> p0
    conv_mma<<<grid, 256, SMEM_CONV>>>(p1h, p1l, wh + 2 * WSTRIDE, wl + 2 * WSTRIDE,
        bg + 512, bb + 512, bm + 512, bv + 512, nullptr, nullptr, yh, yl, nullptr);
    conv_mma<<<grid, 256, SMEM_CONV>>>(yh, yl, wh + 3 * WSTRIDE, wl + 3 * WSTRIDE,
        bg + 768, bb + 768, bm + 768, bv + 768, p1h, p1l, p0h, p0l, nullptr);
    // blk2: p0 -> y ; (y, res p0) -> d_out (fp32 NCHW)
    conv_mma<<<grid, 256, SMEM_CONV>>>(p0h, p0l, wh + 4 * WSTRIDE, wl + 4 * WSTRIDE,
        bg + 1024, bb + 1024, bm + 1024, bv + 1024, nullptr, nullptr, yh, yl, nullptr);
    conv_mma<<<grid, 256, SMEM_CONV>>>(yh, yl, wh + 5 * WSTRIDE, wl + 5 * WSTRIDE,
        bg + 1280, bb + 1280, bm + 1280, bv + 1280, p0h, p0l, nullptr, nullptr, (float*)d_out);
}

// round 15
// speedup vs baseline: 4.3736x; 1.5290x over previous
#include <cuda_runtime.h>
#include <cuda_fp16.h>
#include <cstdint>

typedef unsigned int u32;
typedef unsigned long long u64;

#define H 200
#define W 704
#define HW_TOT (H*W)            // 140800
#define IHP 202
#define IWP 712
#define NPX ((size_t)IHP*IWP)   // padded pixels per plane
#define NCH 256
#define NBOX 128
#define NLAY 6

// ======================= persistent device scratch (zero-init at load) ==============
__device__ __align__(16) __half g_p0h[NPX*NCH], g_p0l[NPX*NCH];
__device__ __align__(16) __half g_p1h[NPX*NCH], g_p1l[NPX*NCH];
__device__ __align__(16) __half g_yh [NPX*NCH], g_yl [NPX*NCH];
__device__ __align__(16) __half g_wh[(size_t)NLAY*9*65536];
__device__ float g_obj[NBOX*NCH];
__device__ float g_edge[NBOX*16];
__device__ int   g_nact;
__device__ int   g_pix[HW_TOT];
__device__ uint4 g_mask[HW_TOT];

// ======================= PTX helpers (plain sm_80-class PTX) =======================
__device__ __forceinline__ u32 smem_to_u32(const void* p) {
    u32 a;
    asm("{ .reg .u64 t; cvta.to.shared.u64 t, %1; cvt.u32.u64 %0, t; }" : "=r"(a) : "l"(p));
    return a;
}
#define SWZ(o) ((o) ^ (((o) >> 3) & 0x70))

#define CP_ASYNC16(dst, src) \
    asm volatile("cp.async.cg.shared.global [%0], [%1], 16;" :: "r"(dst), "l"(src))
#define CP_COMMIT() asm volatile("cp.async.commit_group;" ::: "memory")
#define CP_WAIT1()  asm volatile("cp.async.wait_group 1;" ::: "memory")
#define CP_WAIT0()  asm volatile("cp.async.wait_group 0;" ::: "memory")

#define LDSM4(r, addr) \
    asm volatile("ldmatrix.sync.aligned.m8n8.x4.shared.b16 {%0,%1,%2,%3}, [%4];" \
        : "=r"((r)[0]), "=r"((r)[1]), "=r"((r)[2]), "=r"((r)[3]) : "r"(addr))

#define MMAH(c, a, b0_, b1_) \
    asm volatile("mma.sync.aligned.m16n8k16.row.col.f32.f16.f16.f32 " \
        "{%0,%1,%2,%3},{%4,%5,%6,%7},{%8,%9},{%0,%1,%2,%3};" \
        : "+f"((c)[0]), "+f"((c)[1]), "+f"((c)[2]), "+f"((c)[3]) \
        : "r"((a)[0]), "r"((a)[1]), "r"((a)[2]), "r"((a)[3]), "r"(b0_), "r"(b1_))

__device__ __forceinline__ float hfu(u32 bits16) {
    return __half2float(__ushort_as_half((unsigned short)bits16));
}

// ======================= MLP =======================
__global__ void mlp_kernel(const float* __restrict__ box, const float* __restrict__ score,
                           const float* __restrict__ w1, const float* __restrict__ b1,
                           const float* __restrict__ w2, const float* __restrict__ b2,
                           const float* __restrict__ w3, const float* __restrict__ b3)
{
    __shared__ float f[25];
    __shared__ float h1[256];
    __shared__ float h2[256];
    int n = blockIdx.x, c = threadIdx.x;
    if (c < 25) f[c] = (c < 24) ? box[n * 24 + c] : score[n];
    __syncthreads();
    float a = b1[c];
#pragma unroll
    for (int k = 0; k < 25; ++k) a = fmaf(f[k], w1[k * 256 + c], a);
    h1[c] = fmaxf(a, 0.0f);
    __syncthreads();
    a = b2[c];
    for (int k = 0; k < 256; ++k) a = fmaf(h1[k], w2[k * 256 + c], a);
    h2[c] = fmaxf(a, 0.0f);
    __syncthreads();
    a = b3[c];
    for (int k = 0; k < 256; ++k) a = fmaf(h2[k], w3[k * 256 + c], a);
    g_obj[n * 256 + c] = a * score[n];
}

// ======================= box edges =======================
__global__ void edge_kernel(const float* __restrict__ box)
{
    int n = threadIdx.x;
    if (n == 0) g_nact = 0;
    if (n < NBOX) {
        float gx[4], gy[4];
#pragma unroll
        for (int e = 0; e < 4; ++e) {
            gx[e] = __fdiv_rn(__fsub_rn(box[n * 24 + e * 3 + 0], -140.8f), 0.4f);
            gy[e] = __fdiv_rn(__fsub_rn(box[n * 24 + e * 3 + 1], -40.0f), 0.4f);
        }
#pragma unroll
        for (int e = 0; e < 4; ++e) {
            int e1 = (e + 1) & 3;
            g_edge[n * 16 + e * 4 + 0] = gx[e];
            g_edge[n * 16 + e * 4 + 1] = gy[e];
            g_edge[n * 16 + e * 4 + 2] = __fsub_rn(gx[e1], gx[e]);
            g_edge[n * 16 + e * 4 + 3] = __fsub_rn(gy[e1], gy[e]);
        }
    }
}

// ======================= zero p0 planes =======================
__global__ void zero2_kernel(uint4* a, uint4* b, size_t n4)
{
    size_t i = (size_t)blockIdx.x * blockDim.x + threadIdx.x;
    size_t st = (size_t)gridDim.x * blockDim.x;
    uint4 z = make_uint4(0, 0, 0, 0);
    for (; i < n4; i += st) { a[i] = z; b[i] = z; }
}

// ======================= raster mask + compaction =======================
__global__ void mask_kernel()
{
    __shared__ float se[NBOX * 16];
    int tid = threadIdx.x;
    for (int i = tid; i < NBOX * 16; i += blockDim.x) se[i] = g_edge[i];
    __syncthreads();

    int p = blockIdx.x * 256 + tid;
    if (p >= HW_TOT) return;
    int h = p / W;
    int w = p - h * W;
    float cy = (float)h + 0.5f;
    float cx = (float)w + 0.5f;

    unsigned mw[4];
    int cnt = 0;
#pragma unroll
    for (int wi = 0; wi < 4; ++wi) {
        unsigned m = 0;
        for (int b = 0; b < 32; ++b) {
            int n = wi * 32 + b;
            const float* e = &se[n * 16];
            bool ins = true;
#pragma unroll
            for (int k = 0; k < 4; ++k) {
                float ax = e[k * 4 + 0], ay = e[k * 4 + 1];
                float vx = e[k * 4 + 2], vy = e[k * 4 + 3];
                float c = __fsub_rn(__fmul_rn(vx, __fsub_rn(cy, ay)),
                                    __fmul_rn(vy, __fsub_rn(cx, ax)));
                ins = ins && (c >= 0.0f);
            }
            if (ins) m |= (1u << b);
        }
        mw[wi] = m;
        cnt += __popc(m);
    }
    if (cnt) {
        int pos = atomicAdd(&g_nact, 1);
        g_pix[pos] = p;
        g_mask[pos] = make_uint4(mw[0], mw[1], mw[2], mw[3]);
    }
}

// ======================= scatter into p0 (fp16 hi/lo NHWC) =======================
__global__ void fill_kernel()
{
    int c = threadIdx.x;
    int nact = g_nact;
    for (int i = blockIdx.x; i < nact; i += gridDim.x) {
        int p = g_pix[i];
        uint4 mm = g_mask[i];
        int cnt = __popc(mm.x) + __popc(mm.y) + __popc(mm.z) + __popc(mm.w);
        float acc = 0.0f;
        unsigned m;
        m = mm.x; while (m) { int b = __ffs(m) - 1; m &= m - 1; acc += g_obj[(b)      * NCH + c]; }
        m = mm.y; while (m) { int b = __ffs(m) - 1; m &= m - 1; acc += g_obj[(b + 32) * NCH + c]; }
        m = mm.z; while (m) { int b = __ffs(m) - 1; m &= m - 1; acc += g_obj[(b + 64) * NCH + c]; }
        m = mm.w; while (m) { int b = __ffs(m) - 1; m &= m - 1; acc += g_obj[(b + 96) * NCH + c]; }
        float v = acc / (float)cnt;
        __half hb = __float2half_rn(v);
        __half lb = __float2half_rn(v - __half2float(hb));
        int h = p / W;
        int w = p - h * W;
        size_t o = ((size_t)(h + 1) * IWP + (w + 4)) * NCH + c;
        g_p0h[o] = hb;
        g_p0l[o] = lb;
    }
}

// ======================= weight convert fp32 -> fp16 (single limb), [l][tap][co][ci] ==
__global__ void wsplit_kernel(const float* __restrict__ cw)
{
    int idx = blockIdx.x * 256 + threadIdx.x;
    if (idx >= NLAY * 65536) return;
    int l = idx >> 16;
    int r = idx & 65535;           // co*256 + ci
    int co = r >> 8, ci = r & 255;
    const float* src = cw + (((size_t)l * 256 + co) * 256 + ci) * 9;
#pragma unroll
    for (int t = 0; t < 9; ++t) {
        g_wh[(size_t)(l * 9 + t) * 65536 + r] = __float2half_rn(src[t]);
    }
}

// ======================= fp16 mma conv3x3 + BN (+res) + ReLU =======================
// CTA: 256 thr (8 warps, 2 wm x 4 wn; warp tile m=32 x n=64), 2 CTAs/SM.
// Tile: M=64 px x N=256 co. 36 stages = 9 taps x 4 ci-chunks(64).
// Stage: Ah 8K | Al 8K | Bh 32K = 48KB, double buffered (96KB/CTA).
// 2 emulation passes: C = Ah*Bh + Al*Bh (A 2-limb fp16, B 1-limb fp16).
#define STG 49152
#define SMEM_CONV (2*STG + 2048 + 128)

__device__ __forceinline__ void issue_stage(
    u32 db, int buf, int it, int h0, int w0, int tid,
    const __half* __restrict__ inH, const __half* __restrict__ inL,
    const __half* __restrict__ wH)
{
    int tap = it >> 2, q = it & 3;
    int kh = tap / 3, kw = tap - kh * 3;
    int ci0 = q * 64;
    u32 Ab = db + buf * STG;
    // Ah/Al: 64 px rows x 128B each; 512 chunks per plane, 2/thread per plane
    size_t abase = ((size_t)(h0 + kh) * IWP + (size_t)(w0 + 3 + kw)) * NCH + ci0;
#pragma unroll
    for (int k = 0; k < 2; ++k) {
        int idx = tid + k * 256;           // 0..511
        int m = idx >> 3, j = idx & 7;
        size_t gb = abase + (size_t)m * NCH + j * 8;
        u32 off = SWZ((u32)(m * 128 + j * 16));
        CP_ASYNC16(Ab + off,        inH + gb);
        CP_ASYNC16(Ab + 8192 + off, inL + gb);
    }
    // Bh: 256 co rows x 128B; 2048 chunks, 8/thread
    size_t wbase = (size_t)tap * 65536 + ci0;
    u32 Bb = Ab + 16384;
#pragma unroll
    for (int k = 0; k < 8; ++k) {
        int idx = tid + k * 256;           // 0..2047
        int co = idx >> 3, j = idx & 7;
        CP_ASYNC16(Bb + SWZ((u32)(co * 128 + j * 16)), wH + wbase + (size_t)co * NCH + j * 8);
    }
}

__global__ __launch_bounds__(256, 2)
void conv_mma(const __half* __restrict__ inH, const __half* __restrict__ inL,
              const __half* __restrict__ wH,
              const float* __restrict__ bng, const float* __restrict__ bnb,
              const float* __restrict__ bnm, const float* __restrict__ bnv,
              const __half* resH, const __half* resL,
              __half* outH, __half* outL, float* outF)
{
    extern __shared__ char smem_raw[];
    u32 sb = smem_to_u32(smem_raw);
    u32 pd = (128u - (sb & 127u)) & 127u;
    char* dyn = smem_raw + pd;
    u32 db = sb + pd;
    float* ssc = (float*)(dyn + 2 * STG);
    float* ssh = ssc + 256;

    int tid  = threadIdx.x;
    int lane = tid & 31, warp = tid >> 5;
    int wm = warp & 1, wn = warp >> 1;          // 2 x 4 warp grid
    int h0 = blockIdx.y;
    int w0 = blockIdx.x * 64;                   // 11 * 64 = 704 exact

    {   // BN affine per channel
        int c = tid;
        float sc = bng[c] * rsqrtf(bnv[c] + 1e-5f);
        ssc[c] = sc;
        ssh[c] = bnb[c] - bnm[c] * sc;
    }

    float acc[2][8][4];
#pragma unroll
    for (int a = 0; a < 2; ++a)
#pragma unroll
        for (int b = 0; b < 8; ++b)
#pragma unroll
            for (int c = 0; c < 4; ++c) acc[a][b][c] = 0.0f;

    issue_stage(db, 0, 0, h0, w0, tid, inH, inL, wH);
    CP_COMMIT();

    int lrow = lane & 15;
    int lkb  = (lane >> 4) << 4;       // 0 or 16 bytes (k0/k8)

    for (int it = 0; it < 36; ++it) {
        if (it + 1 < 36) {
            issue_stage(db, (it + 1) & 1, it + 1, h0, w0, tid, inH, inL, wH);
            CP_COMMIT();
            CP_WAIT1();
        } else {
            CP_WAIT0();
        }
        __syncthreads();

        u32 Ab = db + (it & 1) * STG;
        u32 Bb = Ab + 16384;

#pragma unroll
        for (int st = 0; st < 4; ++st) {
            int kb = st * 32 + lkb;
            u32 afh[2][4], afl[2][4];
#pragma unroll
            for (int mf = 0; mf < 2; ++mf) {
                u32 ro = (u32)((wm * 32 + mf * 16 + lrow) * 128);
                LDSM4(afh[mf], Ab + SWZ(ro + kb));
                LDSM4(afl[mf], Ab + 8192 + SWZ(ro + kb));
            }
#pragma unroll
            for (int bp = 0; bp < 4; ++bp) {
                u32 bh[4];
                LDSM4(bh, Bb + SWZ((u32)((wn * 64 + bp * 16 + lrow) * 128 + kb)));
#pragma unroll
                for (int mf = 0; mf < 2; ++mf) {
                    MMAH(acc[mf][2 * bp],     afh[mf], bh[0], bh[2]);
                    MMAH(acc[mf][2 * bp + 1], afh[mf], bh[1], bh[3]);
                }
#pragma unroll
                for (int mf = 0; mf < 2; ++mf) {
                    MMAH(acc[mf][2 * bp],     afl[mf], bh[0], bh[2]);
                    MMAH(acc[mf][2 * bp + 1], afl[mf], bh[1], bh[3]);
                }
            }
        }
        __syncthreads();
    }

    // ---- epilogue: BN, residual, ReLU, store ----
#pragma unroll
    for (int mf = 0; mf < 2; ++mf) {
#pragma unroll
        for (int r2 = 0; r2 < 2; ++r2) {
            int m = wm * 32 + mf * 16 + (lane >> 2) + r2 * 8;
            int wpix = w0 + m;
            size_t pb = ((size_t)(h0 + 1) * IWP + (size_t)(wpix + 4)) * NCH;
#pragma unroll
            for (int a = 0; a < 8; ++a) {
                int n = wn * 64 + a * 8 + (lane & 3) * 2;
                float v0 = fmaf(acc[mf][a][r2 * 2 + 0], ssc[n],     ssh[n]);
                float v1 = fmaf(acc[mf][a][r2 * 2 + 1], ssc[n + 1], ssh[n + 1]);
                if (resH) {
                    u32 rh = *(const u32*)((const char*)resH + (pb + n) * 2);
                    u32 rl = *(const u32*)((const char*)resL + (pb + n) * 2);
                    v0 += hfu(rh & 0xffffu) + hfu(rl & 0xffffu);
                    v1 += hfu(rh >> 16)     + hfu(rl >> 16);
                }
                v0 = fmaxf(v0, 0.0f);
                v1 = fmaxf(v1, 0.0f);
                if (outH) {
                    __half hb0 = __float2half_rn(v0);
                    __half hb1 = __float2half_rn(v1);
                    __half lb0 = __float2half_rn(v0 - __half2float(hb0));
                    __half lb1 = __float2half_rn(v1 - __half2float(hb1));
                    u32 hp = (u32)__half_as_ushort(hb0) | ((u32)__half_as_ushort(hb1) << 16);
                    u32 lp = (u32)__half_as_ushort(lb0) | ((u32)__half_as_ushort(lb1) << 16);
                    *(u32*)((char*)outH + (pb + n) * 2) = hp;
                    *(u32*)((char*)outL + (pb + n) * 2) = lp;
                } else {
                    outF[(size_t)n * HW_TOT       + (size_t)h0 * W + wpix] = v0;
                    outF[(size_t)(n + 1) * HW_TOT + (size_t)h0 * W + wpix] = v1;
                }
            }
        }
    }
}

// ======================= host launcher =======================
extern "C" void kernel_launch(void* const* d_in, const int* in_sizes, int n_in,
                              void* d_out, int out_size)
{
    const float* box   = (const float*)d_in[0];
    const float* score = (const float*)d_in[1];
    const float* w1 = (const float*)d_in[2];
    const float* b1 = (const float*)d_in[3];
    const float* w2 = (const float*)d_in[4];
    const float* b2 = (const float*)d_in[5];
    const float* w3 = (const float*)d_in[6];
    const float* b3 = (const float*)d_in[7];
    const float* cw = (const float*)d_in[8];
    const float* bg = (const float*)d_in[9];
    const float* bb = (const float*)d_in[10];
    const float* bm = (const float*)d_in[11];
    const float* bv = (const float*)d_in[12];

    cudaFuncSetAttribute(conv_mma, cudaFuncAttributeMaxDynamicSharedMemorySize, SMEM_CONV);

    __half *p0h, *p0l, *p1h, *p1l, *yh, *yl, *wh;
    cudaGetSymbolAddress((void**)&p0h, g_p0h);
    cudaGetSymbolAddress((void**)&p0l, g_p0l);
    cudaGetSymbolAddress((void**)&p1h, g_p1h);
    cudaGetSymbolAddress((void**)&p1l, g_p1l);
    cudaGetSymbolAddress((void**)&yh,  g_yh);
    cudaGetSymbolAddress((void**)&yl,  g_yl);
    cudaGetSymbolAddress((void**)&wh,  g_wh);

    mlp_kernel<<<128, 256>>>(box, score, w1, b1, w2, b2, w3, b3);
    edge_kernel<<<1, 128>>>(box);
    wsplit_kernel<<<(NLAY * 65536 + 255) / 256, 256>>>(cw);
    zero2_kernel<<<2048, 256>>>((uint4*)p0h, (uint4*)p0l, NPX * NCH / 8);
    mask_kernel<<<HW_TOT / 256, 256>>>();
    fill_kernel<<<1024, 256>>>();

    dim3 grid(11, 200);      // 11 w-tiles(64) x 200 rows
    const size_t WSTRIDE = (size_t)9 * 65536;
    // blk0: p0 -> y ; (y, res p0) -> p1
    conv_mma<<<grid, 256, SMEM_CONV>>>(p0h, p0l, wh + 0 * WSTRIDE,
        bg + 0, bb + 0, bm + 0, bv + 0, nullptr, nullptr, yh, yl, nullptr);
    conv_mma<<<grid, 256, SMEM_CONV>>>(yh, yl, wh + 1 * WSTRIDE,
        bg + 256, bb + 256, bm + 256, bv + 256, p0h, p0l, p1h, p1l, nullptr);
    // blk1: p1 -> y ; (y, res p1) -> p0
    conv_mma<<<grid, 256, SMEM_CONV>>>(p1h, p1l, wh + 2 * WSTRIDE,
        bg + 512, bb + 512, bm + 512, bv + 512, nullptr, nullptr, yh, yl, nullptr);
    conv_mma<<<grid, 256, SMEM_CONV>>>(yh, yl, wh + 3 * WSTRIDE,
        bg + 768, bb + 768, bm + 768, bv + 768, p1h, p1l, p0h, p0l, nullptr);
    // blk2: p0 -> y ; (y, res p0) -> d_out (fp32 NCHW)
    conv_mma<<<grid, 256, SMEM_CONV>>>(p0h, p0l, wh + 4 * WSTRIDE,
        bg + 1024, bb + 1024, bm + 1024, bv + 1024, nullptr, nullptr, yh, yl, nullptr);
    conv_mma<<<grid, 256, SMEM_CONV>>>(yh, yl, wh + 5 * WSTRIDE,
        bg + 1280, bb + 1280, bm + 1280, bv + 1280, p0h, p0l, nullptr, nullptr, (float*)d_out);
}

// round 16
// speedup vs baseline: 7.8708x; 1.7996x over previous
#include <cuda_runtime.h>
#include <cuda_fp16.h>
#include <cstdint>

typedef unsigned int u32;
typedef unsigned long long u64;

#define H 200
#define W 704
#define HW_TOT (H*W)            // 140800
#define IHP 202
#define IWP 712
#define NPX ((size_t)IHP*IWP)   // padded pixels per plane
#define NCH 256
#define NBOX 128
#define NLAY 6

// ======================= persistent device scratch (zero-init at load) ==============
__device__ __align__(16) __half g_p0[NPX*NCH];
__device__ __align__(16) __half g_p1[NPX*NCH];
__device__ __align__(16) __half g_y [NPX*NCH];
__device__ __align__(16) __half g_wh[(size_t)NLAY*9*65536];
__device__ float g_obj[NBOX*NCH];
__device__ float g_edge[NBOX*16];
__device__ int   g_nact;
__device__ int   g_pix[HW_TOT];
__device__ uint4 g_mask[HW_TOT];

// ======================= PTX helpers (plain sm_80-class PTX) =======================
__device__ __forceinline__ u32 smem_to_u32(const void* p) {
    u32 a;
    asm("{ .reg .u64 t; cvta.to.shared.u64 t, %1; cvt.u32.u64 %0, t; }" : "=r"(a) : "l"(p));
    return a;
}
#define SWZ(o) ((o) ^ (((o) >> 3) & 0x70))

#define CP_ASYNC16(dst, src) \
    asm volatile("cp.async.cg.shared.global [%0], [%1], 16;" :: "r"(dst), "l"(src))
#define CP_COMMIT() asm volatile("cp.async.commit_group;" ::: "memory")
#define CP_WAIT1()  asm volatile("cp.async.wait_group 1;" ::: "memory")
#define CP_WAIT0()  asm volatile("cp.async.wait_group 0;" ::: "memory")

#define LDSM4(r, addr) \
    asm volatile("ldmatrix.sync.aligned.m8n8.x4.shared.b16 {%0,%1,%2,%3}, [%4];" \
        : "=r"((r)[0]), "=r"((r)[1]), "=r"((r)[2]), "=r"((r)[3]) : "r"(addr))

#define MMAH(c, a, b0_, b1_) \
    asm volatile("mma.sync.aligned.m16n8k16.row.col.f32.f16.f16.f32 " \
        "{%0,%1,%2,%3},{%4,%5,%6,%7},{%8,%9},{%0,%1,%2,%3};" \
        : "+f"((c)[0]), "+f"((c)[1]), "+f"((c)[2]), "+f"((c)[3]) \
        : "r"((a)[0]), "r"((a)[1]), "r"((a)[2]), "r"((a)[3]), "r"(b0_), "r"(b1_))

__device__ __forceinline__ float hfu(u32 bits16) {
    return __half2float(__ushort_as_half((unsigned short)bits16));
}

// ======================= MLP =======================
__global__ void mlp_kernel(const float* __restrict__ box, const float* __restrict__ score,
                           const float* __restrict__ w1, const float* __restrict__ b1,
                           const float* __restrict__ w2, const float* __restrict__ b2,
                           const float* __restrict__ w3, const float* __restrict__ b3)
{
    __shared__ float f[25];
    __shared__ float h1[256];
    __shared__ float h2[256];
    int n = blockIdx.x, c = threadIdx.x;
    if (c < 25) f[c] = (c < 24) ? box[n * 24 + c] : score[n];
    __syncthreads();
    float a = b1[c];
#pragma unroll
    for (int k = 0; k < 25; ++k) a = fmaf(f[k], w1[k * 256 + c], a);
    h1[c] = fmaxf(a, 0.0f);
    __syncthreads();
    a = b2[c];
    for (int k = 0; k < 256; ++k) a = fmaf(h1[k], w2[k * 256 + c], a);
    h2[c] = fmaxf(a, 0.0f);
    __syncthreads();
    a = b3[c];
    for (int k = 0; k < 256; ++k) a = fmaf(h2[k], w3[k * 256 + c], a);
    g_obj[n * 256 + c] = a * score[n];
}

// ======================= box edges =======================
__global__ void edge_kernel(const float* __restrict__ box)
{
    int n = threadIdx.x;
    if (n == 0) g_nact = 0;
    if (n < NBOX) {
        float gx[4], gy[4];
#pragma unroll
        for (int e = 0; e < 4; ++e) {
            gx[e] = __fdiv_rn(__fsub_rn(box[n * 24 + e * 3 + 0], -140.8f), 0.4f);
            gy[e] = __fdiv_rn(__fsub_rn(box[n * 24 + e * 3 + 1], -40.0f), 0.4f);
        }
#pragma unroll
        for (int e = 0; e < 4; ++e) {
            int e1 = (e + 1) & 3;
            g_edge[n * 16 + e * 4 + 0] = gx[e];
            g_edge[n * 16 + e * 4 + 1] = gy[e];
            g_edge[n * 16 + e * 4 + 2] = __fsub_rn(gx[e1], gx[e]);
            g_edge[n * 16 + e * 4 + 3] = __fsub_rn(gy[e1], gy[e]);
        }
    }
}

// ======================= zero p0 plane =======================
__global__ void zero_kernel(uint4* a, size_t n4)
{
    size_t i = (size_t)blockIdx.x * blockDim.x + threadIdx.x;
    size_t st = (size_t)gridDim.x * blockDim.x;
    uint4 z = make_uint4(0, 0, 0, 0);
    for (; i < n4; i += st) a[i] = z;
}

// ======================= raster mask + compaction =======================
__global__ void mask_kernel()
{
    __shared__ float se[NBOX * 16];
    int tid = threadIdx.x;
    for (int i = tid; i < NBOX * 16; i += blockDim.x) se[i] = g_edge[i];
    __syncthreads();

    int p = blockIdx.x * 256 + tid;
    if (p >= HW_TOT) return;
    int h = p / W;
    int w = p - h * W;
    float cy = (float)h + 0.5f;
    float cx = (float)w + 0.5f;

    unsigned mw[4];
    int cnt = 0;
#pragma unroll
    for (int wi = 0; wi < 4; ++wi) {
        unsigned m = 0;
        for (int b = 0; b < 32; ++b) {
            int n = wi * 32 + b;
            const float* e = &se[n * 16];
            bool ins = true;
#pragma unroll
            for (int k = 0; k < 4; ++k) {
                float ax = e[k * 4 + 0], ay = e[k * 4 + 1];
                float vx = e[k * 4 + 2], vy = e[k * 4 + 3];
                float c = __fsub_rn(__fmul_rn(vx, __fsub_rn(cy, ay)),
                                    __fmul_rn(vy, __fsub_rn(cx, ax)));
                ins = ins && (c >= 0.0f);
            }
            if (ins) m |= (1u << b);
        }
        mw[wi] = m;
        cnt += __popc(m);
    }
    if (cnt) {
        int pos = atomicAdd(&g_nact, 1);
        g_pix[pos] = p;
        g_mask[pos] = make_uint4(mw[0], mw[1], mw[2], mw[3]);
    }
}

// ======================= scatter into p0 (fp16 NHWC) =======================
__global__ void fill_kernel()
{
    int c = threadIdx.x;
    int nact = g_nact;
    for (int i = blockIdx.x; i < nact; i += gridDim.x) {
        int p = g_pix[i];
        uint4 mm = g_mask[i];
        int cnt = __popc(mm.x) + __popc(mm.y) + __popc(mm.z) + __popc(mm.w);
        float acc = 0.0f;
        unsigned m;
        m = mm.x; while (m) { int b = __ffs(m) - 1; m &= m - 1; acc += g_obj[(b)      * NCH + c]; }
        m = mm.y; while (m) { int b = __ffs(m) - 1; m &= m - 1; acc += g_obj[(b + 32) * NCH + c]; }
        m = mm.z; while (m) { int b = __ffs(m) - 1; m &= m - 1; acc += g_obj[(b + 64) * NCH + c]; }
        m = mm.w; while (m) { int b = __ffs(m) - 1; m &= m - 1; acc += g_obj[(b + 96) * NCH + c]; }
        float v = acc / (float)cnt;
        int h = p / W;
        int w = p - h * W;
        g_p0[((size_t)(h + 1) * IWP + (w + 4)) * NCH + c] = __float2half_rn(v);
    }
}

// ======================= weight convert fp32 -> fp16, [l][tap][co][ci] ==============
__global__ void wsplit_kernel(const float* __restrict__ cw)
{
    int idx = blockIdx.x * 256 + threadIdx.x;
    if (idx >= NLAY * 65536) return;
    int l = idx >> 16;
    int r = idx & 65535;           // co*256 + ci
    int co = r >> 8, ci = r & 255;
    const float* src = cw + (((size_t)l * 256 + co) * 256 + ci) * 9;
#pragma unroll
    for (int t = 0; t < 9; ++t) {
        g_wh[(size_t)(l * 9 + t) * 65536 + r] = __float2half_rn(src[t]);
    }
}

// ======================= fp16 mma conv3x3 + BN (+res) + ReLU =======================
// CTA: 256 thr (8 warps, 2 wm x 4 wn; warp tile m=32 x n=64), 2 CTAs/SM.
// Tile: M=64 px x N=256 co. 36 stages = 9 taps x 4 ci-chunks(64).
// Stage: A 8K | B 32K = 40KB, double buffered (80KB/CTA).
// SINGLE pass: C = A*B (both single-limb fp16; rel_err model ~5e-4).
#define STG 40960
#define SMEM_CONV (2*STG + 2048 + 128)

__device__ __forceinline__ void issue_stage(
    u32 db, int buf, int it, int h0, int w0, int tid,
    const __half* __restrict__ inP, const __half* __restrict__ wH)
{
    int tap = it >> 2, q = it & 3;
    int kh = tap / 3, kw = tap - kh * 3;
    int ci0 = q * 64;
    u32 Ab = db + buf * STG;
    // A: 64 px rows x 128B; 512 chunks, 2/thread
    size_t abase = ((size_t)(h0 + kh) * IWP + (size_t)(w0 + 3 + kw)) * NCH + ci0;
#pragma unroll
    for (int k = 0; k < 2; ++k) {
        int idx = tid + k * 256;           // 0..511
        int m = idx >> 3, j = idx & 7;
        CP_ASYNC16(Ab + SWZ((u32)(m * 128 + j * 16)), inP + abase + (size_t)m * NCH + j * 8);
    }
    // B: 256 co rows x 128B; 2048 chunks, 8/thread
    size_t wbase = (size_t)tap * 65536 + ci0;
    u32 Bb = Ab + 8192;
#pragma unroll
    for (int k = 0; k < 8; ++k) {
        int idx = tid + k * 256;           // 0..2047
        int co = idx >> 3, j = idx & 7;
        CP_ASYNC16(Bb + SWZ((u32)(co * 128 + j * 16)), wH + wbase + (size_t)co * NCH + j * 8);
    }
}

__global__ __launch_bounds__(256, 2)
void conv_mma(const __half* __restrict__ inP, const __half* __restrict__ wH,
              const float* __restrict__ bng, const float* __restrict__ bnb,
              const float* __restrict__ bnm, const float* __restrict__ bnv,
              const __half* resP, __half* outP, float* outF)
{
    extern __shared__ char smem_raw[];
    u32 sb = smem_to_u32(smem_raw);
    u32 pd = (128u - (sb & 127u)) & 127u;
    char* dyn = smem_raw + pd;
    u32 db = sb + pd;
    float* ssc = (float*)(dyn + 2 * STG);
    float* ssh = ssc + 256;

    int tid  = threadIdx.x;
    int lane = tid & 31, warp = tid >> 5;
    int wm = warp & 1, wn = warp >> 1;          // 2 x 4 warp grid
    int h0 = blockIdx.y;
    int w0 = blockIdx.x * 64;                   // 11 * 64 = 704 exact

    {   // BN affine per channel
        int c = tid;
        float sc = bng[c] * rsqrtf(bnv[c] + 1e-5f);
        ssc[c] = sc;
        ssh[c] = bnb[c] - bnm[c] * sc;
    }

    float acc[2][8][4];
#pragma unroll
    for (int a = 0; a < 2; ++a)
#pragma unroll
        for (int b = 0; b < 8; ++b)
#pragma unroll
            for (int c = 0; c < 4; ++c) acc[a][b][c] = 0.0f;

    issue_stage(db, 0, 0, h0, w0, tid, inP, wH);
    CP_COMMIT();

    int lrow = lane & 15;
    int lkb  = (lane >> 4) << 4;       // 0 or 16 bytes (k0/k8)

    for (int it = 0; it < 36; ++it) {
        if (it + 1 < 36) {
            issue_stage(db, (it + 1) & 1, it + 1, h0, w0, tid, inP, wH);
            CP_COMMIT();
            CP_WAIT1();
        } else {
            CP_WAIT0();
        }
        __syncthreads();

        u32 Ab = db + (it & 1) * STG;
        u32 Bb = Ab + 8192;

#pragma unroll
        for (int st = 0; st < 4; ++st) {
            int kb = st * 32 + lkb;
            u32 af[2][4];
#pragma unroll
            for (int mf = 0; mf < 2; ++mf) {
                LDSM4(af[mf], Ab + SWZ((u32)((wm * 32 + mf * 16 + lrow) * 128 + kb)));
            }
#pragma unroll
            for (int bp = 0; bp < 4; ++bp) {
                u32 bf[4];
                LDSM4(bf, Bb + SWZ((u32)((wn * 64 + bp * 16 + lrow) * 128 + kb)));
#pragma unroll
                for (int mf = 0; mf < 2; ++mf) {
                    MMAH(acc[mf][2 * bp],     af[mf], bf[0], bf[2]);
                    MMAH(acc[mf][2 * bp + 1], af[mf], bf[1], bf[3]);
                }
            }
        }
        __syncthreads();
    }

    // ---- epilogue: BN, residual, ReLU, store ----
#pragma unroll
    for (int mf = 0; mf < 2; ++mf) {
#pragma unroll
        for (int r2 = 0; r2 < 2; ++r2) {
            int m = wm * 32 + mf * 16 + (lane >> 2) + r2 * 8;
            int wpix = w0 + m;
            size_t pb = ((size_t)(h0 + 1) * IWP + (size_t)(wpix + 4)) * NCH;
#pragma unroll
            for (int a = 0; a < 8; ++a) {
                int n = wn * 64 + a * 8 + (lane & 3) * 2;
                float v0 = fmaf(acc[mf][a][r2 * 2 + 0], ssc[n],     ssh[n]);
                float v1 = fmaf(acc[mf][a][r2 * 2 + 1], ssc[n + 1], ssh[n + 1]);
                if (resP) {
                    u32 rh = *(const u32*)((const char*)resP + (pb + n) * 2);
                    v0 += hfu(rh & 0xffffu);
                    v1 += hfu(rh >> 16);
                }
                v0 = fmaxf(v0, 0.0f);
                v1 = fmaxf(v1, 0.0f);
                if (outP) {
                    u32 hp = (u32)__half_as_ushort(__float2half_rn(v0))
                           | ((u32)__half_as_ushort(__float2half_rn(v1)) << 16);
                    *(u32*)((char*)outP + (pb + n) * 2) = hp;
                } else {
                    outF[(size_t)n * HW_TOT       + (size_t)h0 * W + wpix] = v0;
                    outF[(size_t)(n + 1) * HW_TOT + (size_t)h0 * W + wpix] = v1;
                }
            }
        }
    }
}

// ======================= host launcher =======================
extern "C" void kernel_launch(void* const* d_in, const int* in_sizes, int n_in,
                              void* d_out, int out_size)
{
    const float* box   = (const float*)d_in[0];
    const float* score = (const float*)d_in[1];
    const float* w1 = (const float*)d_in[2];
    const float* b1 = (const float*)d_in[3];
    const float* w2 = (const float*)d_in[4];
    const float* b2 = (const float*)d_in[5];
    const float* w3 = (const float*)d_in[6];
    const float* b3 = (const float*)d_in[7];
    const float* cw = (const float*)d_in[8];
    const float* bg = (const float*)d_in[9];
    const float* bb = (const float*)d_in[10];
    const float* bm = (const float*)d_in[11];
    const float* bv = (const float*)d_in[12];

    cudaFuncSetAttribute(conv_mma, cudaFuncAttributeMaxDynamicSharedMemorySize, SMEM_CONV);

    __half *p0, *p1, *yP, *wh;
    cudaGetSymbolAddress((void**)&p0, g_p0);
    cudaGetSymbolAddress((void**)&p1, g_p1);
    cudaGetSymbolAddress((void**)&yP, g_y);
    cudaGetSymbolAddress((void**)&wh, g_wh);

    mlp_kernel<<<128, 256>>>(box, score, w1, b1, w2, b2, w3, b3);
    edge_kernel<<<1, 128>>>(box);
    wsplit_kernel<<<(NLAY * 65536 + 255) / 256, 256>>>(cw);
    zero_kernel<<<2048, 256>>>((uint4*)p0, NPX * NCH / 8);
    mask_kernel<<<HW_TOT / 256, 256>>>();
    fill_kernel<<<1024, 256>>>();

    dim3 grid(11, 200);      // 11 w-tiles(64) x 200 rows
    const size_t WSTRIDE = (size_t)9 * 65536;
    // blk0: p0 -> y ; (y, res p0) -> p1
    conv_mma<<<grid, 256, SMEM_CONV>>>(p0, wh + 0 * WSTRIDE,
        bg + 0, bb + 0, bm + 0, bv + 0, nullptr, yP, nullptr);
    conv_mma<<<grid, 256, SMEM_CONV>>>(yP, wh + 1 * WSTRIDE,
        bg + 256, bb + 256, bm + 256, bv + 256, p0, p1, nullptr);
    // blk1: p1 -> y ; (y, res p1) -> p0
    conv_mma<<<grid, 256, SMEM_CONV>>>(p1, wh + 2 * WSTRIDE,
        bg + 512, bb + 512, bm + 512, bv + 512, nullptr, yP, nullptr);
    conv_mma<<<grid, 256, SMEM_CONV>>>(yP, wh + 3 * WSTRIDE,
        bg + 768, bb + 768, bm + 768, bv + 768, p1, p0, nullptr);
    // blk2: p0 -> y ; (y, res p0) -> d_out (fp32 NCHW)
    conv_mma<<<grid, 256, SMEM_CONV>>>(p0, wh + 4 * WSTRIDE,
        bg + 1024, bb + 1024, bm + 1024, bv + 1024, nullptr, yP, nullptr);
    conv_mma<<<grid, 256, SMEM_CONV>>>(yP, wh + 5 * WSTRIDE,
        bg + 1280, bb + 1280, bm + 1280, bv + 1280, p0, nullptr, (float*)d_out);
}